// round 13
// baseline (speedup 1.0000x reference)
#include <cuda_runtime.h>
#include <cuda_bf16.h>
#include <cstdint>

// RecurrentGCN (DCRNN GRU step, K=1) on GB300 — Round 11: warp-level mma.sync
// (HMMA bf16, sm_80+ PTX — tcgen05 is 'a'-gated and the harness PTX target is
// plain sm_103, so tcgen05 is unavailable in this toolchain).
// GEMM1: xh[128,48] @ B1^T[48,96] -> [z|r|x@Whx], bf16 2-term split (3 HMMA/term-step)
// GEMM2: rh[128,32] @ B2^T[32,32] accumulated into h~ block.
// output: concat( out[N,2], h_new[N,32] )  (float32)

#define F_IN 10
#define HID  32
#define DIN  42
#define NPC  128
#define TB   128

// SMEM layout (bytes). bf16 tiles: row stride 56 bf16 = 112B (conflict-free
// for the .32 fragment loads: 28 words/row, rows 0..7 -> word offsets
// {0,28,24,20,16,12,8,4} mod 32 — disjoint 4-word groups).
// f32 h tile: stride 40 floats = 160B (conflict-free for .64 frag access).
#define A_STRIDE 112
#define H_STRIDE 160
#define SM_AH   0
#define SM_AL   (SM_AH + 128*A_STRIDE)
#define SM_B1H  (SM_AL + 128*A_STRIDE)
#define SM_B1L  (SM_B1H + 96*A_STRIDE)
#define SM_B2H  (SM_B1L + 96*A_STRIDE)
#define SM_B2L  (SM_B2H + 32*A_STRIDE)
#define SM_H    (SM_B2L + 32*A_STRIDE)
#define SM_TOTAL (SM_H + 128*H_STRIDE)        // 77824 B

// staging (written by prep kernel): bf16x2 k-pairs, [tier][n][kpair]
__device__ uint32_t g_B1[2][96][24];          // n<96 (z|r|Whx), K=48 (42 padded)
__device__ uint32_t g_B2[2][32][16];          // Whh^T, K=32
// small fp32: [0..31]=b_z [32..63]=b_r [64..95]=b_h [96..159]=W_lin [160..161]=b_lin
__device__   __align__(16) float g_wstage[192];
__constant__ __align__(16) float c_small[192];

// ---- math helpers ----
__device__ __forceinline__ float ex2f(float x){ float y; asm("ex2.approx.f32 %0, %1;" : "=f"(y) : "f"(x)); return y; }
__device__ __forceinline__ float rcpf(float x){ float y; asm("rcp.approx.f32 %0, %1;" : "=f"(y) : "f"(x)); return y; }
__device__ __forceinline__ float sigm(float x){ return rcpf(1.0f + ex2f(-1.4426950408889634f * x)); }
__device__ __forceinline__ float tanh_fast(float x){ return fmaf(2.0f, sigm(2.0f*x), -1.0f); }

__device__ __forceinline__ uint32_t pack_bf2(float a, float b){
    __nv_bfloat162 p = __floats2bfloat162_rn(a, b);   // .x = a (low half)
    return *reinterpret_cast<uint32_t*>(&p);
}
__device__ __forceinline__ void split_pair(float a, float b, uint32_t& hi, uint32_t& lo){
    __nv_bfloat16 ah = __float2bfloat16(a), bh = __float2bfloat16(b);
    hi = pack_bf2(__bfloat162float(ah), __bfloat162float(bh));
    lo = pack_bf2(a - __bfloat162float(ah), b - __bfloat162float(bh));
}

// HMMA m16n8k16 bf16, f32 accum. Fragment maps (Ampere+ standard):
//  A: a0=(r=lq,k=kq*2..+1) a1=(r+8,klo) a2=(r,k+8) a3=(r+8,k+8)
//  B: b0=(k=kq*2..+1, n=lq) b1=(k+8, n)
//  D: d0,d1=(r=lq, c=kq*2, c+1)  d2,d3=(r+8, ...)
__device__ __forceinline__ void mma_bf16(float* d, const uint32_t* a, uint32_t b0, uint32_t b1){
    asm volatile("mma.sync.aligned.m16n8k16.row.col.f32.bf16.bf16.f32 "
        "{%0,%1,%2,%3}, {%4,%5,%6,%7}, {%8,%9}, {%0,%1,%2,%3};"
        : "+f"(d[0]),"+f"(d[1]),"+f"(d[2]),"+f"(d[3])
        : "r"(a[0]),"r"(a[1]),"r"(a[2]),"r"(a[3]), "r"(b0),"r"(b1));
}
__device__ __forceinline__ uint32_t ldsu(const char* s, int off){
    return *reinterpret_cast<const uint32_t*>(s + off);
}

// ---------------- prep: build split/transposed B tiles + small consts ----------------
__global__ void prep(const float* __restrict__ Wz, const float* __restrict__ Wr,
                     const float* __restrict__ Wh,
                     const float* __restrict__ bz, const float* __restrict__ br,
                     const float* __restrict__ bh,
                     const float* __restrict__ Wlin, const float* __restrict__ blin)
{
    int t = blockIdx.x * blockDim.x + threadIdx.x;
    const int G = DIN * HID;  // 1344
    if (t < 96 * 24) {        // B1[n][k] = W'[k][n]: n = [z(32)|r(32)|Whx(32)]
        int nn = t / 24, c2 = t % 24;
        float v[2];
        #pragma unroll
        for (int u = 0; u < 2; u++) {
            int k = 2 * c2 + u;
            float w = 0.0f;
            if (k < DIN) {
                if (nn < 32)       w = Wz[k*32 + nn]      + Wz[G + k*32 + nn];
                else if (nn < 64)  w = Wr[k*32 + (nn-32)] + Wr[G + k*32 + (nn-32)];
                else if (k < F_IN) w = Wh[k*32 + (nn-64)] + Wh[G + k*32 + (nn-64)];
            }
            v[u] = w;
        }
        uint32_t hi, lo; split_pair(v[0], v[1], hi, lo);
        g_B1[0][nn][c2] = hi;  g_B1[1][nn][c2] = lo;
    }
    if (t < 32 * 16) {        // B2[n][k] = Whh'[k][n] = Wh'[10+k][n]
        int nn = t / 16, c2 = t % 16;
        float v[2];
        #pragma unroll
        for (int u = 0; u < 2; u++) {
            int k = 2 * c2 + u;
            v[u] = Wh[(F_IN + k)*32 + nn] + Wh[G + (F_IN + k)*32 + nn];
        }
        uint32_t hi, lo; split_pair(v[0], v[1], hi, lo);
        g_B2[0][nn][c2] = hi;  g_B2[1][nn][c2] = lo;
    }
    if (t < 32) { g_wstage[t] = bz[t]; g_wstage[32+t] = br[t]; g_wstage[64+t] = bh[t]; }
    if (t < 64) g_wstage[96 + t] = Wlin[t];
    if (t < 2)  g_wstage[160 + t] = blin[t];
}

// ---------------- main kernel ----------------
__global__ __launch_bounds__(TB)
void dcrnn_mma(const float* __restrict__ x, const float* __restrict__ h,
               float* __restrict__ out, int n)
{
    extern __shared__ char sm[];
    int tid = threadIdx.x;
    int lane = tid & 31, wid = tid >> 5;
    int lq = lane >> 2, kq = lane & 3;
    int wrow = wid * 32;                     // warp w owns rows (== its own tids)
    long node = (long)blockIdx.x * NPC + tid;
    bool valid = node < n;

    // ---- load node inputs ----
    float av[48], hv[HID];
    #pragma unroll
    for (int k = 0; k < 48; k++) av[k] = 0.0f;
    #pragma unroll
    for (int k = 0; k < HID; k++) hv[k] = 0.0f;
    if (valid) {
        const float2* xp = reinterpret_cast<const float2*>(x + node * F_IN);
        #pragma unroll
        for (int k = 0; k < F_IN/2; k++) { float2 v = xp[k]; av[2*k] = v.x; av[2*k+1] = v.y; }
        const float4* hp = reinterpret_cast<const float4*>(h + node * HID);
        #pragma unroll
        for (int k = 0; k < HID/4; k++) {
            float4 v = hp[k];
            hv[4*k]=v.x; hv[4*k+1]=v.y; hv[4*k+2]=v.z; hv[4*k+3]=v.w;
            av[F_IN+4*k]=v.x; av[F_IN+4*k+1]=v.y; av[F_IN+4*k+2]=v.z; av[F_IN+4*k+3]=v.w;
        }
    }

    // ---- stage A tiles (own row), f32 h tile (own row) ----
    #pragma unroll
    for (int c2 = 0; c2 < 24; c2++) {
        uint32_t hi, lo; split_pair(av[2*c2], av[2*c2+1], hi, lo);
        int off = tid * A_STRIDE + c2 * 4;
        *reinterpret_cast<uint32_t*>(sm + SM_AH + off) = hi;
        *reinterpret_cast<uint32_t*>(sm + SM_AL + off) = lo;
    }
    #pragma unroll
    for (int q = 0; q < 8; q++)
        *reinterpret_cast<float4*>(sm + SM_H + tid * H_STRIDE + q * 16) =
            make_float4(hv[4*q], hv[4*q+1], hv[4*q+2], hv[4*q+3]);

    // ---- stage B tiles ----
    for (int idx = tid; idx < 96*24; idx += TB) {
        int nn = idx / 24, c2 = idx % 24;
        int off = nn * A_STRIDE + c2 * 4;
        *reinterpret_cast<uint32_t*>(sm + SM_B1H + off) = g_B1[0][nn][c2];
        *reinterpret_cast<uint32_t*>(sm + SM_B1L + off) = g_B1[1][nn][c2];
    }
    for (int idx = tid; idx < 32*16; idx += TB) {
        int nn = idx / 16, c2 = idx % 16;
        int off = nn * A_STRIDE + c2 * 4;
        *reinterpret_cast<uint32_t*>(sm + SM_B2H + off) = g_B2[0][nn][c2];
        *reinterpret_cast<uint32_t*>(sm + SM_B2L + off) = g_B2[1][nn][c2];
    }
    __syncthreads();

    // ---- cache A fragments (reused by all 3 GEMM1 blocks) ----
    uint32_t afh[2][3][4], afl[2][3][4];
    #pragma unroll
    for (int mi = 0; mi < 2; mi++) {
        #pragma unroll
        for (int ks = 0; ks < 3; ks++) {
            int r0 = wrow + mi*16 + lq;
            int k  = ks*16 + kq*2;
            afh[mi][ks][0] = ldsu(sm, SM_AH + r0*A_STRIDE + k*2);
            afh[mi][ks][1] = ldsu(sm, SM_AH + (r0+8)*A_STRIDE + k*2);
            afh[mi][ks][2] = ldsu(sm, SM_AH + r0*A_STRIDE + (k+8)*2);
            afh[mi][ks][3] = ldsu(sm, SM_AH + (r0+8)*A_STRIDE + (k+8)*2);
            afl[mi][ks][0] = ldsu(sm, SM_AL + r0*A_STRIDE + k*2);
            afl[mi][ks][1] = ldsu(sm, SM_AL + (r0+8)*A_STRIDE + k*2);
            afl[mi][ks][2] = ldsu(sm, SM_AL + r0*A_STRIDE + (k+8)*2);
            afl[mi][ks][3] = ldsu(sm, SM_AL + (r0+8)*A_STRIDE + (k+8)*2);
        }
    }

#define GEMM1_BLOCK(dacc, nbase)                                              \
    {                                                                         \
        _Pragma("unroll")                                                     \
        for (int nj = 0; nj < 4; nj++) {                                      \
            _Pragma("unroll")                                                 \
            for (int ks = 0; ks < 3; ks++) {                                  \
                int nr = (nbase) + nj*8 + lq;                                 \
                int k  = ks*16 + kq*2;                                        \
                uint32_t bh0 = ldsu(sm, SM_B1H + nr*A_STRIDE + k*2);          \
                uint32_t bh1 = ldsu(sm, SM_B1H + nr*A_STRIDE + (k+8)*2);      \
                uint32_t bl0 = ldsu(sm, SM_B1L + nr*A_STRIDE + k*2);          \
                uint32_t bl1 = ldsu(sm, SM_B1L + nr*A_STRIDE + (k+8)*2);      \
                _Pragma("unroll")                                             \
                for (int mi = 0; mi < 2; mi++) {                              \
                    mma_bf16(dacc[mi][nj], afh[mi][ks], bh0, bh1);            \
                    mma_bf16(dacc[mi][nj], afh[mi][ks], bl0, bl1);            \
                    mma_bf16(dacc[mi][nj], afl[mi][ks], bh0, bh1);            \
                }                                                             \
            }                                                                 \
        }                                                                     \
    }

    // ---- GEMM1 r-block (B1 rows 32..63) ----
    float dr[2][4][4];
    #pragma unroll
    for (int mi = 0; mi < 2; mi++)
        #pragma unroll
        for (int nj = 0; nj < 4; nj++)
            #pragma unroll
            for (int q = 0; q < 4; q++) dr[mi][nj][q] = 0.0f;
    GEMM1_BLOCK(dr, 32)

    // ---- epilogue 1: rh = sigm(r + b_r) * h -> bf16 split into A region ----
    #pragma unroll
    for (int mi = 0; mi < 2; mi++) {
        #pragma unroll
        for (int nj = 0; nj < 4; nj++) {
            int c = nj*8 + kq*2;
            float br0 = c_small[32 + c], br1 = c_small[33 + c];
            #pragma unroll
            for (int half = 0; half < 2; half++) {
                int r = wrow + mi*16 + lq + half*8;
                float2 hh = *reinterpret_cast<const float2*>(sm + SM_H + r*H_STRIDE + c*4);
                float rh0 = sigm(dr[mi][nj][2*half]   + br0) * hh.x;
                float rh1 = sigm(dr[mi][nj][2*half+1] + br1) * hh.y;
                uint32_t hi, lo; split_pair(rh0, rh1, hi, lo);
                int off = r*A_STRIDE + c*2;
                *reinterpret_cast<uint32_t*>(sm + SM_AH + off) = hi;
                *reinterpret_cast<uint32_t*>(sm + SM_AL + off) = lo;
            }
        }
    }
    __syncwarp();

    // ---- GEMM1 z-block (rows 0..31) and hx-block (rows 64..95) ----
    float dz[2][4][4], dh[2][4][4];
    #pragma unroll
    for (int mi = 0; mi < 2; mi++)
        #pragma unroll
        for (int nj = 0; nj < 4; nj++)
            #pragma unroll
            for (int q = 0; q < 4; q++) { dz[mi][nj][q] = 0.0f; dh[mi][nj][q] = 0.0f; }
    GEMM1_BLOCK(dz, 0)
    GEMM1_BLOCK(dh, 64)

    // ---- GEMM2: dh += rh[128,32] @ B2^T ----
    {
        uint32_t rfh[2][2][4], rfl[2][2][4];
        #pragma unroll
        for (int mi = 0; mi < 2; mi++) {
            #pragma unroll
            for (int ks = 0; ks < 2; ks++) {
                int r0 = wrow + mi*16 + lq;
                int k  = ks*16 + kq*2;
                rfh[mi][ks][0] = ldsu(sm, SM_AH + r0*A_STRIDE + k*2);
                rfh[mi][ks][1] = ldsu(sm, SM_AH + (r0+8)*A_STRIDE + k*2);
                rfh[mi][ks][2] = ldsu(sm, SM_AH + r0*A_STRIDE + (k+8)*2);
                rfh[mi][ks][3] = ldsu(sm, SM_AH + (r0+8)*A_STRIDE + (k+8)*2);
                rfl[mi][ks][0] = ldsu(sm, SM_AL + r0*A_STRIDE + k*2);
                rfl[mi][ks][1] = ldsu(sm, SM_AL + (r0+8)*A_STRIDE + k*2);
                rfl[mi][ks][2] = ldsu(sm, SM_AL + r0*A_STRIDE + (k+8)*2);
                rfl[mi][ks][3] = ldsu(sm, SM_AL + (r0+8)*A_STRIDE + (k+8)*2);
            }
        }
        #pragma unroll
        for (int nj = 0; nj < 4; nj++) {
            #pragma unroll
            for (int ks = 0; ks < 2; ks++) {
                int nr = nj*8 + lq;
                int k  = ks*16 + kq*2;
                uint32_t bh0 = ldsu(sm, SM_B2H + nr*A_STRIDE + k*2);
                uint32_t bh1 = ldsu(sm, SM_B2H + nr*A_STRIDE + (k+8)*2);
                uint32_t bl0 = ldsu(sm, SM_B2L + nr*A_STRIDE + k*2);
                uint32_t bl1 = ldsu(sm, SM_B2L + nr*A_STRIDE + (k+8)*2);
                #pragma unroll
                for (int mi = 0; mi < 2; mi++) {
                    mma_bf16(dh[mi][nj], rfh[mi][ks], bh0, bh1);
                    mma_bf16(dh[mi][nj], rfh[mi][ks], bl0, bl1);
                    mma_bf16(dh[mi][nj], rfl[mi][ks], bh0, bh1);
                }
            }
        }
    }

    // ---- epilogue 2: h_new = z*h + (1-z)*tanh(pre + b_h) -> f32 into h tile ----
    #pragma unroll
    for (int mi = 0; mi < 2; mi++) {
        #pragma unroll
        for (int nj = 0; nj < 4; nj++) {
            int c = nj*8 + kq*2;
            float bh0 = c_small[64 + c], bh1 = c_small[65 + c];
            #pragma unroll
            for (int half = 0; half < 2; half++) {
                int r = wrow + mi*16 + lq + half*8;
                float2 hh = *reinterpret_cast<const float2*>(sm + SM_H + r*H_STRIDE + c*4);
                float t0 = tanh_fast(dh[mi][nj][2*half]   + bh0);
                float t1 = tanh_fast(dh[mi][nj][2*half+1] + bh1);
                float z0 = sigm(dz[mi][nj][2*half]);
                float z1 = sigm(dz[mi][nj][2*half+1]);
                float hn0 = fmaf(z0, hh.x - t0, t0);
                float hn1 = fmaf(z1, hh.y - t1, t1);
                *reinterpret_cast<float2*>(sm + SM_H + r*H_STRIDE + c*4) = make_float2(hn0, hn1);
            }
        }
    }
    __syncwarp();

    // ---- head: out = ReLU(h_new) @ W_lin^T + b_lin; write h_new ----
    if (valid) {
        float hnv[HID];
        #pragma unroll
        for (int q = 0; q < 8; q++) {
            float4 v = *reinterpret_cast<const float4*>(sm + SM_H + tid * H_STRIDE + q * 16);
            hnv[4*q]=v.x; hnv[4*q+1]=v.y; hnv[4*q+2]=v.z; hnv[4*q+3]=v.w;
        }
        float o0 = c_small[160], o1 = c_small[161];
        #pragma unroll
        for (int j = 0; j < HID; j++) {
            float rel = fmaxf(hnv[j], 0.0f);
            o0 = fmaf(rel, c_small[96 + j], o0);
            o1 = fmaf(rel, c_small[128 + j], o1);
        }
        reinterpret_cast<float2*>(out)[node] = make_float2(o0, o1);
        float4* hop = reinterpret_cast<float4*>(out + (size_t)2 * n + node * HID);
        #pragma unroll
        for (int q = 0; q < 8; q++)
            hop[q] = make_float4(hnv[4*q], hnv[4*q+1], hnv[4*q+2], hnv[4*q+3]);
    }
}

extern "C" void kernel_launch(void* const* d_in, const int* in_sizes, int n_in,
                              void* d_out, int out_size)
{
    const float* x    = (const float*)d_in[0];
    // d_in[1] edge_index, d_in[2] edge_weight: unused (K=1 collapses DConv)
    const float* h    = (const float*)d_in[3];
    const float* Wz   = (const float*)d_in[4];
    const float* bz   = (const float*)d_in[5];
    const float* Wr   = (const float*)d_in[6];
    const float* br   = (const float*)d_in[7];
    const float* Wh   = (const float*)d_in[8];
    const float* bh   = (const float*)d_in[9];
    const float* Wlin = (const float*)d_in[10];
    const float* blin = (const float*)d_in[11];
    float* out = (float*)d_out;

    int n = in_sizes[0] / F_IN;

    void* g_addr = nullptr; void* c_addr = nullptr;
    cudaGetSymbolAddress(&g_addr, g_wstage);
    cudaGetSymbolAddress(&c_addr, c_small);

    prep<<<9, 256>>>(Wz, Wr, Wh, bz, br, bh, Wlin, blin);
    cudaMemcpyAsync(c_addr, g_addr, 192 * sizeof(float), cudaMemcpyDeviceToDevice, 0);

    cudaFuncSetAttribute(dcrnn_mma, cudaFuncAttributeMaxDynamicSharedMemorySize, SM_TOTAL);
    int blocks = (n + NPC - 1) / NPC;
    dcrnn_mma<<<blocks, TB, SM_TOTAL>>>(x, h, out, n);
}

// round 16
// speedup vs baseline: 1.3107x; 1.3107x over previous
#include <cuda_runtime.h>
#include <cuda_bf16.h>
#include <cstdint>

// RecurrentGCN (DCRNN GRU step, K=1) on GB300 — Round 13: HMMA + occupancy.
// R11 was latency-bound at 8 warps/SM (77.8KB smem). This round: 54KB smem ->
// 4 CTAs/SM (16 warps), cp.async B staging, h reloaded from gmem for the blend.
// GEMM1: xh[128,48] @ B1^T[48,96] -> [z|r|x@Whx]  (bf16 hi/lo split, 3 HMMA/step)
// GEMM2: rh[128,32] @ B2^T[32,32] accumulated into h~ block.
// output: concat( out[N,2], h_new[N,32] )  (float32)

#define F_IN 10
#define HID  32
#define DIN  42
#define NPC  128
#define TB   128

// strides (bytes). Conflict-free frag loads need (stride/4) mod 32 in {4,12,20,28}.
#define A_STRIDE  112              // 28 words -> lq*28 mod 32 = {0,28,24,...} ok
#define B2_STRIDE 80               // 20 words -> lq*20 mod 32 = {0,20,8,...} ok
#define EX_STRIDE 272              // 68 words -> 4*tid pattern, conflict-free

#define SM_AH   0
#define SM_AL   14336              // 128*112
#define SM_B    28672
#define SM_B1H  (SM_B)             // 96*112 = 10752
#define SM_B1L  (SM_B + 10752)
#define SM_B2H  (SM_B + 21504)     // 32*80 = 2560
#define SM_B2L  (SM_B + 24064)
#define SM_TOTAL 55296             // 54 KB -> 4 CTAs/SM
#define B_BYTES 26624
// exchange (z,t f32) overlays [0, 128*272) = [0,34816): A + first 6KB of B1H,
// all dead after the post-GEMM2 __syncthreads.

// staging: B tiles pre-strided to the exact smem image (flat cp.async copy)
__device__ __align__(16) uint8_t g_Bs[B_BYTES];
// [0..31]=b_z [32..63]=b_r [64..95]=b_h [96..159]=W_lin [160..161]=b_lin
__device__   __align__(16) float g_wstage[192];
__constant__ __align__(16) float c_small[192];

// ---- math helpers ----
__device__ __forceinline__ float ex2f(float x){ float y; asm("ex2.approx.f32 %0, %1;" : "=f"(y) : "f"(x)); return y; }
__device__ __forceinline__ float rcpf(float x){ float y; asm("rcp.approx.f32 %0, %1;" : "=f"(y) : "f"(x)); return y; }
__device__ __forceinline__ float sigm(float x){ return rcpf(1.0f + ex2f(-1.4426950408889634f * x)); }
__device__ __forceinline__ float tanh_fast(float x){ return fmaf(2.0f, sigm(2.0f*x), -1.0f); }

__device__ __forceinline__ uint32_t pack_bf2(float a, float b){
    __nv_bfloat162 p = __floats2bfloat162_rn(a, b);
    return *reinterpret_cast<uint32_t*>(&p);
}
__device__ __forceinline__ void split_pair(float a, float b, uint32_t& hi, uint32_t& lo){
    __nv_bfloat16 ah = __float2bfloat16(a), bh = __float2bfloat16(b);
    hi = pack_bf2(__bfloat162float(ah), __bfloat162float(bh));
    lo = pack_bf2(a - __bfloat162float(ah), b - __bfloat162float(bh));
}
__device__ __forceinline__ float2 bf2f(uint32_t u){
    __nv_bfloat162 b = *reinterpret_cast<__nv_bfloat162*>(&u);
    return make_float2(__bfloat162float(b.x), __bfloat162float(b.y));
}

// HMMA m16n8k16 bf16, f32 accum (fragment maps verified by R11 pass).
__device__ __forceinline__ void mma_bf16(float* d, const uint32_t* a, uint32_t b0, uint32_t b1){
    asm volatile("mma.sync.aligned.m16n8k16.row.col.f32.bf16.bf16.f32 "
        "{%0,%1,%2,%3}, {%4,%5,%6,%7}, {%8,%9}, {%0,%1,%2,%3};"
        : "+f"(d[0]),"+f"(d[1]),"+f"(d[2]),"+f"(d[3])
        : "r"(a[0]),"r"(a[1]),"r"(a[2]),"r"(a[3]), "r"(b0),"r"(b1));
}
__device__ __forceinline__ uint32_t ldsu(const char* s, int off){
    return *reinterpret_cast<const uint32_t*>(s + off);
}
__device__ __forceinline__ void cpa16(uint32_t s, const void* g){
    asm volatile("cp.async.ca.shared.global [%0], [%1], 16;" :: "r"(s), "l"(g));
}

// ---------------- prep: build pre-strided split B tiles + small consts ----------------
__global__ void prep(const float* __restrict__ Wz, const float* __restrict__ Wr,
                     const float* __restrict__ Wh,
                     const float* __restrict__ bz, const float* __restrict__ br,
                     const float* __restrict__ bh,
                     const float* __restrict__ Wlin, const float* __restrict__ blin)
{
    int t = blockIdx.x * blockDim.x + threadIdx.x;
    const int G = DIN * HID;  // 1344
    if (t < 96 * 24) {        // B1[n][k] = W'[k][n]: n = [z(32)|r(32)|Whx(32)], K pad 48
        int nn = t / 24, c2 = t % 24;
        float v[2];
        #pragma unroll
        for (int u = 0; u < 2; u++) {
            int k = 2 * c2 + u;
            float w = 0.0f;
            if (k < DIN) {
                if (nn < 32)       w = Wz[k*32 + nn]      + Wz[G + k*32 + nn];
                else if (nn < 64)  w = Wr[k*32 + (nn-32)] + Wr[G + k*32 + (nn-32)];
                else if (k < F_IN) w = Wh[k*32 + (nn-64)] + Wh[G + k*32 + (nn-64)];
            }
            v[u] = w;
        }
        uint32_t hi, lo; split_pair(v[0], v[1], hi, lo);
        int off = nn * A_STRIDE + c2 * 4;
        *reinterpret_cast<uint32_t*>(g_Bs + off)          = hi;
        *reinterpret_cast<uint32_t*>(g_Bs + 10752 + off)  = lo;
    }
    if (t < 32 * 16) {        // B2[n][k] = Whh'[k][n] = Wh'[10+k][n], K=32
        int nn = t / 16, c2 = t % 16;
        float v[2];
        #pragma unroll
        for (int u = 0; u < 2; u++) {
            int k = 2 * c2 + u;
            v[u] = Wh[(F_IN + k)*32 + nn] + Wh[G + (F_IN + k)*32 + nn];
        }
        uint32_t hi, lo; split_pair(v[0], v[1], hi, lo);
        int off = nn * B2_STRIDE + c2 * 4;
        *reinterpret_cast<uint32_t*>(g_Bs + 21504 + off) = hi;
        *reinterpret_cast<uint32_t*>(g_Bs + 24064 + off) = lo;
    }
    if (t < 32) { g_wstage[t] = bz[t]; g_wstage[32+t] = br[t]; g_wstage[64+t] = bh[t]; }
    if (t < 64) g_wstage[96 + t] = Wlin[t];
    if (t < 2)  g_wstage[160 + t] = blin[t];
}

// ---------------- main kernel ----------------
__global__ __launch_bounds__(TB, 4)
void dcrnn_mma(const float* __restrict__ x, const float* __restrict__ h,
               float* __restrict__ out, int n)
{
    extern __shared__ char sm[];
    uint32_t sb;
    asm("{ .reg .u64 t; cvta.to.shared.u64 t, %1; cvt.u32.u64 %0, t; }" : "=r"(sb) : "l"(sm));
    int tid = threadIdx.x;
    int lane = tid & 31, wid = tid >> 5;
    int lq = lane >> 2, kq = lane & 3;
    int wrow = wid * 32;
    long node = (long)blockIdx.x * NPC + tid;
    bool valid = node < n;

    // ---- B prefetch via cp.async (overlaps everything below) ----
    #pragma unroll
    for (int o = tid * 16; o < B_BYTES; o += TB * 16)
        cpa16(sb + SM_B + o, g_Bs + o);
    asm volatile("cp.async.commit_group;" ::: "memory");

    // ---- load x,h; stage A = [x|h] bf16 hi/lo (own row) ----
    {
        float av[48];
        #pragma unroll
        for (int k = 0; k < 48; k++) av[k] = 0.0f;
        if (valid) {
            const float2* xp = reinterpret_cast<const float2*>(x + node * F_IN);
            #pragma unroll
            for (int k = 0; k < F_IN/2; k++) { float2 v = xp[k]; av[2*k] = v.x; av[2*k+1] = v.y; }
            const float4* hp = reinterpret_cast<const float4*>(h + node * HID);
            #pragma unroll
            for (int k = 0; k < HID/4; k++) {
                float4 v = hp[k];
                av[F_IN+4*k]=v.x; av[F_IN+4*k+1]=v.y; av[F_IN+4*k+2]=v.z; av[F_IN+4*k+3]=v.w;
            }
        }
        #pragma unroll
        for (int c2 = 0; c2 < 24; c2++) {
            uint32_t hi, lo; split_pair(av[2*c2], av[2*c2+1], hi, lo);
            int off = tid * A_STRIDE + c2 * 4;
            *reinterpret_cast<uint32_t*>(sm + SM_AH + off) = hi;
            *reinterpret_cast<uint32_t*>(sm + SM_AL + off) = lo;
        }
    }
    asm volatile("cp.async.wait_group 0;" ::: "memory");
    __syncthreads();

    // ---- cache A fragments (reused by all 3 GEMM1 blocks) ----
    uint32_t afh[2][3][4], afl[2][3][4];
    #pragma unroll
    for (int mi = 0; mi < 2; mi++) {
        #pragma unroll
        for (int ks = 0; ks < 3; ks++) {
            int r0 = wrow + mi*16 + lq;
            int k  = ks*16 + kq*2;
            afh[mi][ks][0] = ldsu(sm, SM_AH + r0*A_STRIDE + k*2);
            afh[mi][ks][1] = ldsu(sm, SM_AH + (r0+8)*A_STRIDE + k*2);
            afh[mi][ks][2] = ldsu(sm, SM_AH + r0*A_STRIDE + (k+8)*2);
            afh[mi][ks][3] = ldsu(sm, SM_AH + (r0+8)*A_STRIDE + (k+8)*2);
            afl[mi][ks][0] = ldsu(sm, SM_AL + r0*A_STRIDE + k*2);
            afl[mi][ks][1] = ldsu(sm, SM_AL + (r0+8)*A_STRIDE + k*2);
            afl[mi][ks][2] = ldsu(sm, SM_AL + r0*A_STRIDE + (k+8)*2);
            afl[mi][ks][3] = ldsu(sm, SM_AL + (r0+8)*A_STRIDE + (k+8)*2);
        }
    }

#define GEMM1_BLOCK(dacc, nbase)                                              \
    {                                                                         \
        _Pragma("unroll")                                                     \
        for (int nj = 0; nj < 4; nj++) {                                      \
            _Pragma("unroll")                                                 \
            for (int ks = 0; ks < 3; ks++) {                                  \
                int nr = (nbase) + nj*8 + lq;                                 \
                int k  = ks*16 + kq*2;                                        \
                uint32_t bh0 = ldsu(sm, SM_B1H + nr*A_STRIDE + k*2);          \
                uint32_t bh1 = ldsu(sm, SM_B1H + nr*A_STRIDE + (k+8)*2);      \
                uint32_t bl0 = ldsu(sm, SM_B1L + nr*A_STRIDE + k*2);          \
                uint32_t bl1 = ldsu(sm, SM_B1L + nr*A_STRIDE + (k+8)*2);      \
                _Pragma("unroll")                                             \
                for (int mi = 0; mi < 2; mi++) {                              \
                    mma_bf16(dacc[mi][nj], afh[mi][ks], bh0, bh1);            \
                    mma_bf16(dacc[mi][nj], afh[mi][ks], bl0, bl1);            \
                    mma_bf16(dacc[mi][nj], afl[mi][ks], bh0, bh1);            \
                }                                                             \
            }                                                                 \
        }                                                                     \
    }

    // ---- GEMM1 r-block (B1 rows 32..63) ----
    float dr[2][4][4];
    #pragma unroll
    for (int mi = 0; mi < 2; mi++)
        #pragma unroll
        for (int nj = 0; nj < 4; nj++)
            #pragma unroll
            for (int q = 0; q < 4; q++) dr[mi][nj][q] = 0.0f;
    GEMM1_BLOCK(dr, 32)

    // ---- epilogue 1: rh = sigm(r+b_r) * h' -> bf16 split over A cols 0..31 ----
    // h' reconstructed from A tiles cols 10..41 (hi+lo). Read ALL before writes.
    {
        float2 hp[2][4][2];
        #pragma unroll
        for (int mi = 0; mi < 2; mi++)
            #pragma unroll
            for (int nj = 0; nj < 4; nj++)
                #pragma unroll
                for (int half = 0; half < 2; half++) {
                    int r = wrow + mi*16 + lq + half*8;
                    int c = nj*8 + kq*2;
                    float2 a = bf2f(ldsu(sm, SM_AH + r*A_STRIDE + (10+c)*2));
                    float2 b = bf2f(ldsu(sm, SM_AL + r*A_STRIDE + (10+c)*2));
                    hp[mi][nj][half] = make_float2(a.x + b.x, a.y + b.y);
                }
        __syncwarp();
        #pragma unroll
        for (int mi = 0; mi < 2; mi++)
            #pragma unroll
            for (int nj = 0; nj < 4; nj++) {
                int c = nj*8 + kq*2;
                float br0 = c_small[32 + c], br1 = c_small[33 + c];
                #pragma unroll
                for (int half = 0; half < 2; half++) {
                    int r = wrow + mi*16 + lq + half*8;
                    float rh0 = sigm(dr[mi][nj][2*half]   + br0) * hp[mi][nj][half].x;
                    float rh1 = sigm(dr[mi][nj][2*half+1] + br1) * hp[mi][nj][half].y;
                    uint32_t hi, lo; split_pair(rh0, rh1, hi, lo);
                    int off = r*A_STRIDE + c*2;
                    *reinterpret_cast<uint32_t*>(sm + SM_AH + off) = hi;
                    *reinterpret_cast<uint32_t*>(sm + SM_AL + off) = lo;
                }
            }
        __syncwarp();
    }

    // ---- GEMM1 z-block (rows 0..31) and hx-block (rows 64..95) ----
    float dz[2][4][4], dh[2][4][4];
    #pragma unroll
    for (int mi = 0; mi < 2; mi++)
        #pragma unroll
        for (int nj = 0; nj < 4; nj++)
            #pragma unroll
            for (int q = 0; q < 4; q++) { dz[mi][nj][q] = 0.0f; dh[mi][nj][q] = 0.0f; }
    GEMM1_BLOCK(dz, 0)
    GEMM1_BLOCK(dh, 64)

    // ---- GEMM2: dh += rh[128,32] @ B2^T ----
    {
        #pragma unroll
        for (int ks = 0; ks < 2; ks++) {
            uint32_t rfh[2][4], rfl[2][4];
            #pragma unroll
            for (int mi = 0; mi < 2; mi++) {
                int r0 = wrow + mi*16 + lq;
                int k  = ks*16 + kq*2;
                rfh[mi][0] = ldsu(sm, SM_AH + r0*A_STRIDE + k*2);
                rfh[mi][1] = ldsu(sm, SM_AH + (r0+8)*A_STRIDE + k*2);
                rfh[mi][2] = ldsu(sm, SM_AH + r0*A_STRIDE + (k+8)*2);
                rfh[mi][3] = ldsu(sm, SM_AH + (r0+8)*A_STRIDE + (k+8)*2);
                rfl[mi][0] = ldsu(sm, SM_AL + r0*A_STRIDE + k*2);
                rfl[mi][1] = ldsu(sm, SM_AL + (r0+8)*A_STRIDE + k*2);
                rfl[mi][2] = ldsu(sm, SM_AL + r0*A_STRIDE + (k+8)*2);
                rfl[mi][3] = ldsu(sm, SM_AL + (r0+8)*A_STRIDE + (k+8)*2);
            }
            #pragma unroll
            for (int nj = 0; nj < 4; nj++) {
                int nr = nj*8 + lq;
                int k  = ks*16 + kq*2;
                uint32_t bh0 = ldsu(sm, SM_B2H + nr*B2_STRIDE + k*2);
                uint32_t bh1 = ldsu(sm, SM_B2H + nr*B2_STRIDE + (k+8)*2);
                uint32_t bl0 = ldsu(sm, SM_B2L + nr*B2_STRIDE + k*2);
                uint32_t bl1 = ldsu(sm, SM_B2L + nr*B2_STRIDE + (k+8)*2);
                #pragma unroll
                for (int mi = 0; mi < 2; mi++) {
                    mma_bf16(dh[mi][nj], rfh[mi], bh0, bh1);
                    mma_bf16(dh[mi][nj], rfh[mi], bl0, bl1);
                    mma_bf16(dh[mi][nj], rfl[mi], bh0, bh1);
                }
            }
        }
    }

    // All warps done reading A/B1/B2 -> exchange may overlay them.
    __syncthreads();

    // ---- epilogue 2: write z=sigm(z_pre+b_z), t=tanh(h_pre+b_h) to exchange ----
    #pragma unroll
    for (int mi = 0; mi < 2; mi++)
        #pragma unroll
        for (int nj = 0; nj < 4; nj++) {
            int c = nj*8 + kq*2;
            float bz0 = c_small[c],      bz1 = c_small[c+1];
            float bh0 = c_small[64 + c], bh1 = c_small[65 + c];
            #pragma unroll
            for (int half = 0; half < 2; half++) {
                int r = wrow + mi*16 + lq + half*8;
                float z0 = sigm(dz[mi][nj][2*half]   + bz0);
                float z1 = sigm(dz[mi][nj][2*half+1] + bz1);
                float t0 = tanh_fast(dh[mi][nj][2*half]   + bh0);
                float t1 = tanh_fast(dh[mi][nj][2*half+1] + bh1);
                *reinterpret_cast<float2*>(sm + r*EX_STRIDE + c*4)       = make_float2(z0, z1);
                *reinterpret_cast<float2*>(sm + r*EX_STRIDE + 128 + c*4) = make_float2(t0, t1);
            }
        }
    __syncwarp();   // exchange rows of a warp are produced by that same warp

    // ---- row-phase: h_new = z*h + (1-z)*t; head; stores ----
    if (valid) {
        float zt[64];
        #pragma unroll
        for (int q = 0; q < 16; q++) {
            float4 v = *reinterpret_cast<const float4*>(sm + tid*EX_STRIDE + q*16);
            zt[4*q]=v.x; zt[4*q+1]=v.y; zt[4*q+2]=v.z; zt[4*q+3]=v.w;
        }
        const float4* hp = reinterpret_cast<const float4*>(h + node * HID);
        float hn[HID];
        #pragma unroll
        for (int q = 0; q < 8; q++) {
            float4 hv = hp[q];
            hn[4*q]   = fmaf(zt[4*q],   hv.x - zt[32+4*q],   zt[32+4*q]);
            hn[4*q+1] = fmaf(zt[4*q+1], hv.y - zt[33+4*q],   zt[33+4*q]);
            hn[4*q+2] = fmaf(zt[4*q+2], hv.z - zt[34+4*q],   zt[34+4*q]);
            hn[4*q+3] = fmaf(zt[4*q+3], hv.w - zt[35+4*q],   zt[35+4*q]);
        }
        float o0 = c_small[160], o1 = c_small[161];
        #pragma unroll
        for (int j = 0; j < HID; j++) {
            float rel = fmaxf(hn[j], 0.0f);
            o0 = fmaf(rel, c_small[96 + j], o0);
            o1 = fmaf(rel, c_small[128 + j], o1);
        }
        reinterpret_cast<float2*>(out)[node] = make_float2(o0, o1);
        float4* hop = reinterpret_cast<float4*>(out + (size_t)2 * n + node * HID);
        #pragma unroll
        for (int q = 0; q < 8; q++)
            hop[q] = make_float4(hn[4*q], hn[4*q+1], hn[4*q+2], hn[4*q+3]);
    }
}

extern "C" void kernel_launch(void* const* d_in, const int* in_sizes, int n_in,
                              void* d_out, int out_size)
{
    const float* x    = (const float*)d_in[0];
    // d_in[1] edge_index, d_in[2] edge_weight: unused (K=1 collapses DConv)
    const float* h    = (const float*)d_in[3];
    const float* Wz   = (const float*)d_in[4];
    const float* bz   = (const float*)d_in[5];
    const float* Wr   = (const float*)d_in[6];
    const float* br   = (const float*)d_in[7];
    const float* Wh   = (const float*)d_in[8];
    const float* bh   = (const float*)d_in[9];
    const float* Wlin = (const float*)d_in[10];
    const float* blin = (const float*)d_in[11];
    float* out = (float*)d_out;

    int n = in_sizes[0] / F_IN;

    void* g_addr = nullptr; void* c_addr = nullptr;
    cudaGetSymbolAddress(&g_addr, g_wstage);
    cudaGetSymbolAddress(&c_addr, c_small);

    prep<<<9, 256>>>(Wz, Wr, Wh, bz, br, bh, Wlin, blin);
    cudaMemcpyAsync(c_addr, g_addr, 192 * sizeof(float), cudaMemcpyDeviceToDevice, 0);

    cudaFuncSetAttribute(dcrnn_mma, cudaFuncAttributeMaxDynamicSharedMemorySize, SM_TOTAL);
    int blocks = (n + NPC - 1) / NPC;
    dcrnn_mma<<<blocks, TB, SM_TOTAL>>>(x, h, out, n);
}

// round 17
// speedup vs baseline: 1.3832x; 1.0553x over previous
#include <cuda_runtime.h>
#include <cuda_bf16.h>
#include <cstdint>

// RecurrentGCN (DCRNN GRU step, K=1) on GB300 — Round 16: R13 + ldmatrix + STS.128.
// R13 binder was L1tex (73.7%): 4-way-conflicted staging stores + ~400 scalar LDS
// issue slots/thread. This round: ldmatrix.x4 fragment loads (4x fewer instr)
// and STS.128 staging (conflict-free phases). Structure otherwise identical.
// GEMM1: xh[128,48] @ B1^T[48,96] -> [z|r|x@Whx]  (bf16 hi/lo split, 3 HMMA/step)
// GEMM2: rh[128,32] @ B2^T[32,32] accumulated into h~ block.
// output: concat( out[N,2], h_new[N,32] )  (float32)

#define F_IN 10
#define HID  32
#define DIN  42
#define NPC  128
#define TB   128

#define A_STRIDE  112              // 7 x 16B granules/row -> LDSM/STS.128 phase-clean
#define B2_STRIDE 80               // 5 x 16B granules/row
#define EX_STRIDE 272              // 17 granules -> row-phase float4 reads clean

#define SM_AH   0
#define SM_AL   14336              // 128*112
#define SM_B    28672
#define SM_B1H  (SM_B)             // 96*112 = 10752
#define SM_B1L  (SM_B + 10752)
#define SM_B2H  (SM_B + 21504)     // 32*80 = 2560
#define SM_B2L  (SM_B + 24064)
#define SM_TOTAL 55296             // 54 KB -> 4 CTAs/SM
#define B_BYTES 26624
// exchange (z,t f32) overlays [0, 128*272) after the post-GEMM2 __syncthreads.

__device__ __align__(16) uint8_t g_Bs[B_BYTES];   // pre-strided B image
// [0..31]=b_z [32..63]=b_r [64..95]=b_h [96..159]=W_lin [160..161]=b_lin
__device__   __align__(16) float g_wstage[192];
__constant__ __align__(16) float c_small[192];

// ---- math helpers ----
__device__ __forceinline__ float ex2f(float x){ float y; asm("ex2.approx.f32 %0, %1;" : "=f"(y) : "f"(x)); return y; }
__device__ __forceinline__ float rcpf(float x){ float y; asm("rcp.approx.f32 %0, %1;" : "=f"(y) : "f"(x)); return y; }
__device__ __forceinline__ float sigm(float x){ return rcpf(1.0f + ex2f(-1.4426950408889634f * x)); }
__device__ __forceinline__ float tanh_fast(float x){ return fmaf(2.0f, sigm(2.0f*x), -1.0f); }

__device__ __forceinline__ uint32_t pack_bf2(float a, float b){
    __nv_bfloat162 p = __floats2bfloat162_rn(a, b);
    return *reinterpret_cast<uint32_t*>(&p);
}
__device__ __forceinline__ void split_pair(float a, float b, uint32_t& hi, uint32_t& lo){
    __nv_bfloat16 ah = __float2bfloat16(a), bh = __float2bfloat16(b);
    hi = pack_bf2(__bfloat162float(ah), __bfloat162float(bh));
    lo = pack_bf2(a - __bfloat162float(ah), b - __bfloat162float(bh));
}
__device__ __forceinline__ float2 bf2f(uint32_t u){
    __nv_bfloat162 b = *reinterpret_cast<__nv_bfloat162*>(&u);
    return make_float2(__bfloat162float(b.x), __bfloat162float(b.y));
}

// HMMA m16n8k16 bf16, f32 accum (frag maps verified in R11/R13).
__device__ __forceinline__ void mma_bf16(float* d, const uint32_t* a, uint32_t b0, uint32_t b1){
    asm volatile("mma.sync.aligned.m16n8k16.row.col.f32.bf16.bf16.f32 "
        "{%0,%1,%2,%3}, {%4,%5,%6,%7}, {%8,%9}, {%0,%1,%2,%3};"
        : "+f"(d[0]),"+f"(d[1]),"+f"(d[2]),"+f"(d[3])
        : "r"(a[0]),"r"(a[1]),"r"(a[2]),"r"(a[3]), "r"(b0),"r"(b1));
}
// ldmatrix x4: 4 m8n8 b16 matrices; lane group g (lane/8) supplies matrix g's
// row addresses; output reg r[g] is matrix g's fragment.
__device__ __forceinline__ void ldsm4(uint32_t* r, uint32_t a){
    asm volatile("ldmatrix.sync.aligned.m8n8.x4.shared.b16 {%0,%1,%2,%3}, [%4];"
        : "=r"(r[0]),"=r"(r[1]),"=r"(r[2]),"=r"(r[3]) : "r"(a));
}
__device__ __forceinline__ uint32_t ldsu(const char* s, int off){
    return *reinterpret_cast<const uint32_t*>(s + off);
}
__device__ __forceinline__ void cpa16(uint32_t s, const void* g){
    asm volatile("cp.async.ca.shared.global [%0], [%1], 16;" :: "r"(s), "l"(g));
}

// ---------------- prep: pre-strided split B tiles + small consts ----------------
__global__ void prep(const float* __restrict__ Wz, const float* __restrict__ Wr,
                     const float* __restrict__ Wh,
                     const float* __restrict__ bz, const float* __restrict__ br,
                     const float* __restrict__ bh,
                     const float* __restrict__ Wlin, const float* __restrict__ blin)
{
    int t = blockIdx.x * blockDim.x + threadIdx.x;
    const int G = DIN * HID;  // 1344
    if (t < 96 * 24) {        // B1[n][k] = W'[k][n]: n = [z(32)|r(32)|Whx(32)], K pad 48
        int nn = t / 24, c2 = t % 24;
        float v[2];
        #pragma unroll
        for (int u = 0; u < 2; u++) {
            int k = 2 * c2 + u;
            float w = 0.0f;
            if (k < DIN) {
                if (nn < 32)       w = Wz[k*32 + nn]      + Wz[G + k*32 + nn];
                else if (nn < 64)  w = Wr[k*32 + (nn-32)] + Wr[G + k*32 + (nn-32)];
                else if (k < F_IN) w = Wh[k*32 + (nn-64)] + Wh[G + k*32 + (nn-64)];
            }
            v[u] = w;
        }
        uint32_t hi, lo; split_pair(v[0], v[1], hi, lo);
        int off = nn * A_STRIDE + c2 * 4;
        *reinterpret_cast<uint32_t*>(g_Bs + off)          = hi;
        *reinterpret_cast<uint32_t*>(g_Bs + 10752 + off)  = lo;
    }
    if (t < 32 * 16) {        // B2[n][k] = Whh'[k][n] = Wh'[10+k][n], K=32
        int nn = t / 16, c2 = t % 16;
        float v[2];
        #pragma unroll
        for (int u = 0; u < 2; u++) {
            int k = 2 * c2 + u;
            v[u] = Wh[(F_IN + k)*32 + nn] + Wh[G + (F_IN + k)*32 + nn];
        }
        uint32_t hi, lo; split_pair(v[0], v[1], hi, lo);
        int off = nn * B2_STRIDE + c2 * 4;
        *reinterpret_cast<uint32_t*>(g_Bs + 21504 + off) = hi;
        *reinterpret_cast<uint32_t*>(g_Bs + 24064 + off) = lo;
    }
    if (t < 32) { g_wstage[t] = bz[t]; g_wstage[32+t] = br[t]; g_wstage[64+t] = bh[t]; }
    if (t < 64) g_wstage[96 + t] = Wlin[t];
    if (t < 2)  g_wstage[160 + t] = blin[t];
}

// ---------------- main kernel ----------------
__global__ __launch_bounds__(TB, 4)
void dcrnn_mma(const float* __restrict__ x, const float* __restrict__ h,
               float* __restrict__ out, int n)
{
    extern __shared__ char sm[];
    uint32_t sb;
    asm("{ .reg .u64 t; cvta.to.shared.u64 t, %1; cvt.u32.u64 %0, t; }" : "=r"(sb) : "l"(sm));
    int tid = threadIdx.x;
    int lane = tid & 31, wid = tid >> 5;
    int lq = lane >> 2, kq = lane & 3;
    int grp = lane >> 3, rin = lane & 7;          // ldmatrix addressing
    int wrow = wid * 32;
    long node = (long)blockIdx.x * NPC + tid;
    bool valid = node < n;

    // per-thread invariant ldmatrix offsets
    // A-type x4 (a0=(r,klo) a1=(r+8,klo) a2=(r,khi) a3=(r+8,khi)):
    const int a_off = ((grp & 1) * 8 + rin) * A_STRIDE + (grp >> 1) * 16;
    // B1 x4 ({bh0,bh1,bl0,bl1} across hi/lo tiers):
    const int b1_off = (grp < 2 ? SM_B1H : SM_B1L) + rin * A_STRIDE + (grp & 1) * 16;
    // B2 x4:
    const int b2_off = (grp < 2 ? SM_B2H : SM_B2L) + rin * B2_STRIDE + (grp & 1) * 16;

    // ---- B prefetch via cp.async ----
    #pragma unroll
    for (int o = tid * 16; o < B_BYTES; o += TB * 16)
        cpa16(sb + SM_B + o, g_Bs + o);
    asm volatile("cp.async.commit_group;" ::: "memory");

    // ---- load x,h; stage A = [x|h] bf16 hi/lo via STS.128 (conflict-free phases) ----
    {
        float av[48];
        #pragma unroll
        for (int k = 0; k < 48; k++) av[k] = 0.0f;
        if (valid) {
            const float2* xp = reinterpret_cast<const float2*>(x + node * F_IN);
            #pragma unroll
            for (int k = 0; k < F_IN/2; k++) { float2 v = xp[k]; av[2*k] = v.x; av[2*k+1] = v.y; }
            const float4* hp = reinterpret_cast<const float4*>(h + node * HID);
            #pragma unroll
            for (int k = 0; k < HID/4; k++) {
                float4 v = hp[k];
                av[F_IN+4*k]=v.x; av[F_IN+4*k+1]=v.y; av[F_IN+4*k+2]=v.z; av[F_IN+4*k+3]=v.w;
            }
        }
        uint32_t hw[24], lw[24];
        #pragma unroll
        for (int c2 = 0; c2 < 24; c2++) split_pair(av[2*c2], av[2*c2+1], hw[c2], lw[c2]);
        uint4* dh4 = reinterpret_cast<uint4*>(sm + SM_AH + tid * A_STRIDE);
        uint4* dl4 = reinterpret_cast<uint4*>(sm + SM_AL + tid * A_STRIDE);
        #pragma unroll
        for (int q = 0; q < 6; q++) {
            dh4[q] = make_uint4(hw[4*q], hw[4*q+1], hw[4*q+2], hw[4*q+3]);
            dl4[q] = make_uint4(lw[4*q], lw[4*q+1], lw[4*q+2], lw[4*q+3]);
        }
    }
    asm volatile("cp.async.wait_group 0;" ::: "memory");
    __syncthreads();

    // ---- cache A fragments via ldmatrix (2 tiers x 2 mi x 3 ks = 12 x4) ----
    uint32_t afh[2][3][4], afl[2][3][4];
    #pragma unroll
    for (int mi = 0; mi < 2; mi++) {
        #pragma unroll
        for (int ks = 0; ks < 3; ks++) {
            int base = (wrow + mi*16) * A_STRIDE + ks*32 + a_off;
            ldsm4(afh[mi][ks], sb + SM_AH + base);
            ldsm4(afl[mi][ks], sb + SM_AL + base);
        }
    }

#define GEMM1_BLOCK(dacc, nbase)                                              \
    {                                                                         \
        _Pragma("unroll")                                                     \
        for (int nj = 0; nj < 4; nj++) {                                      \
            _Pragma("unroll")                                                 \
            for (int ks = 0; ks < 3; ks++) {                                  \
                uint32_t bb[4];                                               \
                ldsm4(bb, sb + b1_off + ((nbase) + nj*8) * A_STRIDE + ks*32); \
                _Pragma("unroll")                                             \
                for (int mi = 0; mi < 2; mi++) {                              \
                    mma_bf16(dacc[mi][nj], afh[mi][ks], bb[0], bb[1]);        \
                    mma_bf16(dacc[mi][nj], afh[mi][ks], bb[2], bb[3]);        \
                    mma_bf16(dacc[mi][nj], afl[mi][ks], bb[0], bb[1]);        \
                }                                                             \
            }                                                                 \
        }                                                                     \
    }

    // ---- GEMM1 r-block (B1 rows 32..63) ----
    float dr[2][4][4];
    #pragma unroll
    for (int mi = 0; mi < 2; mi++)
        #pragma unroll
        for (int nj = 0; nj < 4; nj++)
            #pragma unroll
            for (int q = 0; q < 4; q++) dr[mi][nj][q] = 0.0f;
    GEMM1_BLOCK(dr, 32)

    // ---- epilogue 1: rh = sigm(r+b_r) * h' -> bf16 split over A cols 0..31 ----
    // h' reconstructed from A tiles cols 10..41 (hi+lo). Read ALL before writes.
    {
        float2 hp[2][4][2];
        #pragma unroll
        for (int mi = 0; mi < 2; mi++)
            #pragma unroll
            for (int nj = 0; nj < 4; nj++)
                #pragma unroll
                for (int half = 0; half < 2; half++) {
                    int r = wrow + mi*16 + lq + half*8;
                    int c = nj*8 + kq*2;
                    float2 a = bf2f(ldsu(sm, SM_AH + r*A_STRIDE + (10+c)*2));
                    float2 b = bf2f(ldsu(sm, SM_AL + r*A_STRIDE + (10+c)*2));
                    hp[mi][nj][half] = make_float2(a.x + b.x, a.y + b.y);
                }
        __syncwarp();
        #pragma unroll
        for (int mi = 0; mi < 2; mi++)
            #pragma unroll
            for (int nj = 0; nj < 4; nj++) {
                int c = nj*8 + kq*2;
                float br0 = c_small[32 + c], br1 = c_small[33 + c];
                #pragma unroll
                for (int half = 0; half < 2; half++) {
                    int r = wrow + mi*16 + lq + half*8;
                    float rh0 = sigm(dr[mi][nj][2*half]   + br0) * hp[mi][nj][half].x;
                    float rh1 = sigm(dr[mi][nj][2*half+1] + br1) * hp[mi][nj][half].y;
                    uint32_t hi, lo; split_pair(rh0, rh1, hi, lo);
                    int off = r*A_STRIDE + c*2;
                    *reinterpret_cast<uint32_t*>(sm + SM_AH + off) = hi;
                    *reinterpret_cast<uint32_t*>(sm + SM_AL + off) = lo;
                }
            }
        __syncwarp();
    }

    // ---- GEMM1 z-block (rows 0..31) and hx-block (rows 64..95) ----
    float dz[2][4][4], dh[2][4][4];
    #pragma unroll
    for (int mi = 0; mi < 2; mi++)
        #pragma unroll
        for (int nj = 0; nj < 4; nj++)
            #pragma unroll
            for (int q = 0; q < 4; q++) { dz[mi][nj][q] = 0.0f; dh[mi][nj][q] = 0.0f; }
    GEMM1_BLOCK(dz, 0)
    GEMM1_BLOCK(dh, 64)

    // ---- GEMM2: dh += rh[128,32] @ B2^T (ldmatrix frags) ----
    {
        #pragma unroll
        for (int ks = 0; ks < 2; ks++) {
            uint32_t rfh[2][4], rfl[2][4];
            #pragma unroll
            for (int mi = 0; mi < 2; mi++) {
                int base = (wrow + mi*16) * A_STRIDE + ks*32 + a_off;
                ldsm4(rfh[mi], sb + SM_AH + base);
                ldsm4(rfl[mi], sb + SM_AL + base);
            }
            #pragma unroll
            for (int nj = 0; nj < 4; nj++) {
                uint32_t bb[4];
                ldsm4(bb, sb + b2_off + nj*8*B2_STRIDE + ks*32);
                #pragma unroll
                for (int mi = 0; mi < 2; mi++) {
                    mma_bf16(dh[mi][nj], rfh[mi], bb[0], bb[1]);
                    mma_bf16(dh[mi][nj], rfh[mi], bb[2], bb[3]);
                    mma_bf16(dh[mi][nj], rfl[mi], bb[0], bb[1]);
                }
            }
        }
    }

    // All warps done reading A/B1/B2 -> exchange may overlay them.
    __syncthreads();

    // ---- epilogue 2: write z=sigm(z_pre+b_z), t=tanh(h_pre+b_h) to exchange ----
    #pragma unroll
    for (int mi = 0; mi < 2; mi++)
        #pragma unroll
        for (int nj = 0; nj < 4; nj++) {
            int c = nj*8 + kq*2;
            float bz0 = c_small[c],      bz1 = c_small[c+1];
            float bh0 = c_small[64 + c], bh1 = c_small[65 + c];
            #pragma unroll
            for (int half = 0; half < 2; half++) {
                int r = wrow + mi*16 + lq + half*8;
                float z0 = sigm(dz[mi][nj][2*half]   + bz0);
                float z1 = sigm(dz[mi][nj][2*half+1] + bz1);
                float t0 = tanh_fast(dh[mi][nj][2*half]   + bh0);
                float t1 = tanh_fast(dh[mi][nj][2*half+1] + bh1);
                *reinterpret_cast<float2*>(sm + r*EX_STRIDE + c*4)       = make_float2(z0, z1);
                *reinterpret_cast<float2*>(sm + r*EX_STRIDE + 128 + c*4) = make_float2(t0, t1);
            }
        }
    __syncwarp();   // exchange rows of a warp are produced by that same warp

    // ---- row-phase: h_new = z*h + (1-z)*t; head; stores ----
    if (valid) {
        float zt[64];
        #pragma unroll
        for (int q = 0; q < 16; q++) {
            float4 v = *reinterpret_cast<const float4*>(sm + tid*EX_STRIDE + q*16);
            zt[4*q]=v.x; zt[4*q+1]=v.y; zt[4*q+2]=v.z; zt[4*q+3]=v.w;
        }
        const float4* hp = reinterpret_cast<const float4*>(h + node * HID);
        float hn[HID];
        #pragma unroll
        for (int q = 0; q < 8; q++) {
            float4 hv = hp[q];
            hn[4*q]   = fmaf(zt[4*q],   hv.x - zt[32+4*q],   zt[32+4*q]);
            hn[4*q+1] = fmaf(zt[4*q+1], hv.y - zt[33+4*q],   zt[33+4*q]);
            hn[4*q+2] = fmaf(zt[4*q+2], hv.z - zt[34+4*q],   zt[34+4*q]);
            hn[4*q+3] = fmaf(zt[4*q+3], hv.w - zt[35+4*q],   zt[35+4*q]);
        }
        float o0 = c_small[160], o1 = c_small[161];
        #pragma unroll
        for (int j = 0; j < HID; j++) {
            float rel = fmaxf(hn[j], 0.0f);
            o0 = fmaf(rel, c_small[96 + j], o0);
            o1 = fmaf(rel, c_small[128 + j], o1);
        }
        reinterpret_cast<float2*>(out)[node] = make_float2(o0, o1);
        float4* hop = reinterpret_cast<float4*>(out + (size_t)2 * n + node * HID);
        #pragma unroll
        for (int q = 0; q < 8; q++)
            hop[q] = make_float4(hn[4*q], hn[4*q+1], hn[4*q+2], hn[4*q+3]);
    }
}

extern "C" void kernel_launch(void* const* d_in, const int* in_sizes, int n_in,
                              void* d_out, int out_size)
{
    const float* x    = (const float*)d_in[0];
    // d_in[1] edge_index, d_in[2] edge_weight: unused (K=1 collapses DConv)
    const float* h    = (const float*)d_in[3];
    const float* Wz   = (const float*)d_in[4];
    const float* bz   = (const float*)d_in[5];
    const float* Wr   = (const float*)d_in[6];
    const float* br   = (const float*)d_in[7];
    const float* Wh   = (const float*)d_in[8];
    const float* bh   = (const float*)d_in[9];
    const float* Wlin = (const float*)d_in[10];
    const float* blin = (const float*)d_in[11];
    float* out = (float*)d_out;

    int n = in_sizes[0] / F_IN;

    void* g_addr = nullptr; void* c_addr = nullptr;
    cudaGetSymbolAddress(&g_addr, g_wstage);
    cudaGetSymbolAddress(&c_addr, c_small);

    prep<<<9, 256>>>(Wz, Wr, Wh, bz, br, bh, Wlin, blin);
    cudaMemcpyAsync(c_addr, g_addr, 192 * sizeof(float), cudaMemcpyDeviceToDevice, 0);

    cudaFuncSetAttribute(dcrnn_mma, cudaFuncAttributeMaxDynamicSharedMemorySize, SM_TOTAL);
    int blocks = (n + NPC - 1) / NPC;
    dcrnn_mma<<<blocks, TB, SM_TOTAL>>>(x, h, out, n);
}